// round 14
// baseline (speedup 1.0000x reference)
#include <cuda_runtime.h>
#include <cuda_fp16.h>
#include <cstdint>

#define NB 4
#define NN 4096
#define ND 256
#define SCL2 0.0901684403f   // (1/16) * log2(e)
#define S64 64.0f
#define NCTA 304             // 2 CTAs/SM x 152 SMs (GB300)
#define NTILES 2112          // 528 triangular tiles x 4 batches

// ---------------------------------------------------------------------------
// Device scratch
// ---------------------------------------------------------------------------
__device__ __align__(16) __half g_Xh[NB * NN * ND];
__device__ __align__(16) __half g_Xl[NB * NN * ND];
__device__ __align__(16) __half g_Wh[3 * ND * ND];
__device__ __align__(16) __half g_Qh[NB * NN * ND];
__device__ __align__(16) __half g_Kh[NB * NN * ND];
__device__ __align__(16) __half g_Vh[NB * NN * ND];         // V projection, fp16
__device__ __align__(16) __half g_VTh[NB * ND * NN];        // [b][d][m] scaled
__device__ __align__(16) __half g_Eh[(size_t)NB * NN * NN]; // 134 MB, = E/64
__device__ float g_denom[NB * NN];                          // scaled: sum(E)/64
__device__ float g_V0[NB * ND];                             // V'[m=0][d]

// ---------------------------------------------------------------------------
// PTX helpers
// ---------------------------------------------------------------------------
__device__ __forceinline__ uint32_t smem_u32(const void* p) {
    uint32_t a;
    asm("{ .reg .u64 t; cvta.to.shared.u64 t, %1; cvt.u32.u64 %0, t; }"
        : "=r"(a) : "l"(p));
    return a;
}

#define CP_ASYNC16(s, g) \
    asm volatile("cp.async.cg.shared.global [%0], [%1], 16;" :: "r"(s), "l"(g) : "memory")
#define CP_ASYNC16_CA(s, g) \
    asm volatile("cp.async.ca.shared.global [%0], [%1], 16;" :: "r"(s), "l"(g) : "memory")
#define CP_COMMIT asm volatile("cp.async.commit_group;" ::: "memory")

__device__ __forceinline__ void ldsm4(uint32_t* r, uint32_t addr) {
    asm volatile("ldmatrix.sync.aligned.m8n8.x4.shared.b16 {%0,%1,%2,%3}, [%4];"
                 : "=r"(r[0]), "=r"(r[1]), "=r"(r[2]), "=r"(r[3]) : "r"(addr));
}

__device__ __forceinline__ void mma_f16(float* c, const uint32_t* a, const uint32_t* b) {
    asm volatile(
        "mma.sync.aligned.m16n8k16.row.col.f32.f16.f16.f32 "
        "{%0,%1,%2,%3}, {%4,%5,%6,%7}, {%8,%9}, {%0,%1,%2,%3};"
        : "+f"(c[0]), "+f"(c[1]), "+f"(c[2]), "+f"(c[3])
        : "r"(a[0]), "r"(a[1]), "r"(a[2]), "r"(a[3]), "r"(b[0]), "r"(b[1]));
}

// single-MUFU packed exponential: e = 2^z for two halfs
__device__ __forceinline__ uint32_t ex2_f16x2(uint32_t z) {
    uint32_t r;
    asm("ex2.approx.f16x2 %0, %1;" : "=r"(r) : "r"(z));
    return r;
}

__device__ __forceinline__ void splith(float v, __half& h, __half& l) {
    h = __float2half_rn(v);
    l = __float2half_rn(v - __half2float(h));
}

// ---------------------------------------------------------------------------
// Tiles: 128 rows x 64 cols fp16, SMEM row pitch 72 elems (144 B), BCF.
// ---------------------------------------------------------------------------
#define PITCH 72
#define TILEB (128 * PITCH * 2)  // 18432

template <bool CA>
__device__ __forceinline__ void ld_tile(uint32_t sbase, const __half* src,
                                        int row0, int ld, int k0) {
    const int t = threadIdx.x;
#pragma unroll
    for (int h = 0; h < 4; ++h) {
        const int c = t + h * 256;
        const int row = c >> 3, seg = c & 7;
        const char* g = (const char*)src + ((size_t)(row0 + row) * ld + k0 + seg * 8) * 2;
        const uint32_t s = sbase + (row * PITCH + seg * 8) * 2;
        if (CA) { CP_ASYNC16_CA(s, g); } else { CP_ASYNC16(s, g); }
    }
}

// ---------------------------------------------------------------------------
// Generic NT fp16 mainloop (qkv / out_g), BM=BN=128, BK=64, 8 warps.
// Single-sync per chunk: wait -> syncthreads -> prefetch -> compute.
// CH=1: Ah.Bh | CH=2: (Ah+Al).Bh.  CAB: use .ca (L1) for the B operand.
// ---------------------------------------------------------------------------
template <int CH, int STAGES, bool CAB>
__device__ __forceinline__ void gemm_ml(
    const __half* Ah, const __half* Al, const __half* Bh,
    int rowA0, int ldA, int rowB0, int ldB,
    int c0, int c1, char* smp, float acc[2][8][4])
{
    constexpr int NT = (CH == 1) ? 2 : 3;
    constexpr int STG = NT * TILEB;
    constexpr int BOFF = (CH >= 2) ? 2 * TILEB : TILEB;
    const uint32_t sb = smem_u32(smp);
    const int wid = threadIdx.x >> 5, lane = threadIdx.x & 31;
    const int mbase = (wid >> 1) * 32, nbase = (wid & 1) * 64;

#pragma unroll
    for (int i = 0; i < 2; ++i)
#pragma unroll
        for (int j = 0; j < 8; ++j)
#pragma unroll
            for (int k = 0; k < 4; ++k) acc[i][j][k] = 0.0f;

    auto stage_ld = [&](int i, int s) {
        const uint32_t b = sb + s * STG;
        const int k0 = i * 64;
        ld_tile<false>(b, Ah, rowA0, ldA, k0);
        if (CH >= 2) ld_tile<false>(b + TILEB, Al, rowA0, ldA, k0);
        ld_tile<CAB>(b + BOFF, Bh, rowB0, ldB, k0);
    };

#pragma unroll
    for (int p = 0; p < STAGES - 1; ++p) {
        if (c0 + p < c1) stage_ld(c0 + p, p);
        CP_COMMIT;
    }

    for (int i = c0; i < c1; ++i) {
        asm volatile("cp.async.wait_group %0;" :: "n"(STAGES - 2));
        __syncthreads();
        // prefetch (separated from readers of its target buffer by the sync)
        const int pi = i + STAGES - 1;
        if (pi < c1) stage_ld(pi, (pi - c0) % STAGES);
        CP_COMMIT;
        const uint32_t bA = sb + ((i - c0) % STAGES) * STG;
        const uint32_t bB = bA + BOFF;
#pragma unroll
        for (int ks = 0; ks < 4; ++ks) {
            const int koff = ks * 16;
            uint32_t ah[2][4], al[2][4], bh[4][4];
#pragma unroll
            for (int mf = 0; mf < 2; ++mf) {
                const uint32_t ad = bA +
                    ((mbase + mf * 16 + (lane & 15)) * PITCH + koff + (lane >> 4) * 8) * 2;
                ldsm4(ah[mf], ad);
                if (CH >= 2) ldsm4(al[mf], ad + TILEB);
            }
#pragma unroll
            for (int nq = 0; nq < 4; ++nq) {
                const uint32_t bd = bB +
                    ((nbase + nq * 16 + (lane & 7) + ((lane >> 4) & 1) * 8) * PITCH +
                     koff + ((lane >> 3) & 1) * 8) * 2;
                ldsm4(bh[nq], bd);
            }
#pragma unroll
            for (int mf = 0; mf < 2; ++mf)
#pragma unroll
                for (int nf = 0; nf < 8; ++nf) {
                    uint32_t* pb = &bh[nf >> 1][(nf & 1) * 2];
                    mma_f16(acc[mf][nf], ah[mf], pb);
                    if (CH >= 2) mma_f16(acc[mf][nf], al[mf], pb);
                }
        }
    }
    __syncthreads();  // protect last buffers until all warps done (paranoia)
}

#define QK_SMEM (2 * 3 * TILEB)            // 110592
#define E_SMEM  (3 * 2 * TILEB)            // 110592
#define O_SMEM  (3 * 2 * TILEB + 512)      // 111104

// ---------------------------------------------------------------------------
// Fused prep: X split + FULL d_out zero | W fp16 | denom init
// ---------------------------------------------------------------------------
__global__ void prep_kernel(const float* __restrict__ x,
                            const float* __restrict__ Wq,
                            const float* __restrict__ Wk,
                            const float* __restrict__ Wv,
                            float* __restrict__ outp) {
    const int blk = blockIdx.x, t = threadIdx.x;
    if (blk < 4096) {
        const int i = blk * 256 + t;
        float4 v = ((const float4*)x)[i];
        __align__(8) __half h[4], l[4];
        splith(v.x, h[0], l[0]); splith(v.y, h[1], l[1]);
        splith(v.z, h[2], l[2]); splith(v.w, h[3], l[3]);
        ((uint2*)g_Xh)[i] = *(uint2*)h;
        ((uint2*)g_Xl)[i] = *(uint2*)l;
        ((float4*)outp)[i] = make_float4(0.f, 0.f, 0.f, 0.f);
    } else if (blk < 4288) {
        const int w = blk - 4096;
        const int z = w >> 6;
        const int i = (w & 63) * 256 + t;
        const float* W = (z == 0) ? Wq : (z == 1) ? Wk : Wv;
        float4 v = ((const float4*)W)[i];
        __align__(8) __half h[4];
        h[0] = __float2half_rn(v.x); h[1] = __float2half_rn(v.y);
        h[2] = __float2half_rn(v.z); h[3] = __float2half_rn(v.w);
        ((uint2*)(g_Wh + (size_t)z * ND * ND))[i] = *(uint2*)h;
    } else {
        const int i = (blk - 4288) * 256 + t;
        g_denom[i] = ((i & (NN - 1)) == 0) ? 62.0f : 0.0f;
    }
}

// ---------------------------------------------------------------------------
// V' = V * rcp(64*denom) -> transpose [b][d][m] fp16; also V'[0][d].
// ---------------------------------------------------------------------------
__global__ __launch_bounds__(256) void scale_t_g() {
    __shared__ float tile[64][65];
    __shared__ float rs[64];
    const int b = blockIdx.z;
    const int m0 = blockIdx.x * 64, d0 = blockIdx.y * 64;
    const int t = threadIdx.x;

    if (t < 64) rs[t] = __frcp_rn(S64 * g_denom[b * NN + m0 + t]);
    {
        const int m = t >> 2, ds = (t & 3) * 16;
        const __half* src = g_Vh + ((size_t)b * NN + m0 + m) * ND + d0 + ds;
        uint4 v0 = *(const uint4*)src;
        uint4 v1 = *(const uint4*)(src + 8);
        const __half* hp0 = (const __half*)&v0;
        const __half* hp1 = (const __half*)&v1;
#pragma unroll
        for (int k = 0; k < 8; ++k) tile[m][ds + k] = __half2float(hp0[k]);
#pragma unroll
        for (int k = 0; k < 8; ++k) tile[m][ds + 8 + k] = __half2float(hp1[k]);
    }
    __syncthreads();
    {
        const int d = t >> 2, ms = (t & 3) * 16;
        __align__(16) __half o[16];
#pragma unroll
        for (int k = 0; k < 16; ++k)
            o[k] = __float2half_rn(tile[ms + k][d] * rs[ms + k]);
        __half* dst = g_VTh + ((size_t)b * ND + d0 + d) * NN + m0 + ms;
        *(uint4*)dst = ((uint4*)o)[0];
        *(uint4*)(dst + 8) = ((uint4*)o)[1];
    }
    if (m0 == 0 && (t & 3) == 0) {
        const int d = t >> 2;
        g_V0[b * ND + d0 + d] = tile[0][d] * rs[0];
    }
}

// ---------------------------------------------------------------------------
// Kernel A: unified QKV projections (all 2-chain). grid (128, 2, 3)
// ---------------------------------------------------------------------------
__global__ __launch_bounds__(256, 2) void qkv_g() {
    extern __shared__ __align__(16) char sm[];
    const int z = blockIdx.z;
    const int tok0 = blockIdx.x * 128;
    const int c0b = blockIdx.y * 128;
    float acc[2][8][4];
    gemm_ml<2, 2, true>(g_Xh, g_Xl, g_Wh + (size_t)z * ND * ND,
                        tok0, ND, c0b, ND, 0, ND / 64, sm, acc);

    const int wid = threadIdx.x >> 5, lane = threadIdx.x & 31;
    const int mbase = (wid >> 1) * 32, nbase = (wid & 1) * 64;
    __half* dst = (z == 0) ? g_Qh : (z == 1) ? g_Kh : g_Vh;
#pragma unroll
    for (int mf = 0; mf < 2; ++mf)
#pragma unroll
        for (int nf = 0; nf < 8; ++nf) {
            const int tok = tok0 + mbase + mf * 16 + (lane >> 2);
            const int ch = c0b + nbase + nf * 8 + (lane & 3) * 2;
            float* c = acc[mf][nf];
            *(__half2*)&dst[(size_t)tok * ND + ch] = __floats2half2_rn(c[0], c[1]);
            *(__half2*)&dst[(size_t)(tok + 8) * ND + ch] = __floats2half2_rn(c[2], c[3]);
        }
}

// ---------------------------------------------------------------------------
// Kernel B: persistent E kernel. grid (NCTA). Each CTA consumes a strided
// list of triangular tiles (over all 4 batches) as ONE continuous 3-stage
// cp.async stream; single sync per chunk; epilogue at each tile boundary.
// ---------------------------------------------------------------------------
__device__ __forceinline__ float maskexp_s(int qn, int km, float z) {
    return (qn < km) ? exp2f(fmaf(z, SCL2, -6.0f)) : (km == 0 ? 0.015625f : 0.0f);
}

__global__ __launch_bounds__(256, 2) void e_g() {
    extern __shared__ __align__(16) char sm[];
    const int bx = blockIdx.x;
    const int nt = (NTILES - bx + NCTA - 1) / NCTA;  // tiles for this CTA
    const uint32_t sb = smem_u32(sm);
    const int wid = threadIdx.x >> 5, lane = threadIdx.x & 31;
    const int mbase = (wid >> 1) * 32, nbase = (wid & 1) * 64;

    // decoded tile state, two slots (tile parity)
    int ms[2], ns[2], dgs[2];
    size_t qko[2], eo[2];
    int dno[2];

    auto dec = [&](int i) {
        if (i >= nt) return;
        const int slot = i & 1;
        const int t = bx + NCTA * i;
        const int b = t / 528;
        const int tt = t - 528 * b;
        int it = (int)((sqrtf(8.0f * tt + 1.0f) - 1.0f) * 0.5f);
        while ((it + 1) * (it + 2) / 2 <= tt) ++it;
        while (it * (it + 1) / 2 > tt) --it;
        const int jt = tt - it * (it + 1) / 2;
        ms[slot] = it * 128;
        ns[slot] = jt * 128;
        dgs[slot] = (it == jt);
        qko[slot] = (size_t)b * NN * ND;
        eo[slot] = (size_t)b * NN * NN;
        dno[slot] = b * NN;
    };

    auto stage_ld = [&](int q) {
        const int slot = (q >> 2) & 1;
        const int k0 = (q & 3) * 64;
        const uint32_t base = sb + (q % 3) * (2 * TILEB);
        ld_tile<false>(base, g_Qh + qko[slot], ns[slot], ND, k0);
        ld_tile<true>(base + TILEB, g_Kh + qko[slot], ms[slot], ND, k0);
    };

    float acc[2][8][4];
#pragma unroll
    for (int i = 0; i < 2; ++i)
#pragma unroll
        for (int j = 0; j < 8; ++j)
#pragma unroll
            for (int k = 0; k < 4; ++k) acc[i][j][k] = 0.0f;

    auto epi = [&](int slot) {
        const int m0 = ms[slot], n0 = ns[slot], dgf = dgs[slot];
        __half* Eb = g_Eh + eo[slot];
        float* dn = g_denom + dno[slot] + m0;
#pragma unroll
        for (int nf = 0; nf < 8; ++nf) {
            const int kb = m0 + nbase + nf * 8 + (lane & 3) * 2;
            float cs0 = 0.f, cs1 = 0.f;
#pragma unroll
            for (int mf = 0; mf < 2; ++mf) {
                const int qa = n0 + mbase + mf * 16 + (lane >> 2);
                float* c = acc[mf][nf];
                if (!dgf) {
                    __half2 ha = __floats2half2_rn(fmaf(c[0], SCL2, -6.0f),
                                                   fmaf(c[1], SCL2, -6.0f));
                    __half2 hb = __floats2half2_rn(fmaf(c[2], SCL2, -6.0f),
                                                   fmaf(c[3], SCL2, -6.0f));
                    uint32_t ea = ex2_f16x2(*(uint32_t*)&ha);
                    uint32_t eb = ex2_f16x2(*(uint32_t*)&hb);
                    *(uint32_t*)&Eb[(size_t)qa * NN + kb] = ea;
                    *(uint32_t*)&Eb[(size_t)(qa + 8) * NN + kb] = eb;
                    float2 fa = __half22float2(*(__half2*)&ea);
                    float2 fb = __half22float2(*(__half2*)&eb);
                    cs0 += fa.x + fb.x;
                    cs1 += fa.y + fb.y;
                } else {
                    const float e0 = maskexp_s(qa, kb, c[0]);
                    const float e1 = maskexp_s(qa, kb + 1, c[1]);
                    const float e2 = maskexp_s(qa + 8, kb, c[2]);
                    const float e3 = maskexp_s(qa + 8, kb + 1, c[3]);
                    *(__half2*)&Eb[(size_t)qa * NN + kb] = __floats2half2_rn(e0, e1);
                    *(__half2*)&Eb[(size_t)(qa + 8) * NN + kb] = __floats2half2_rn(e2, e3);
                    cs0 += e0 + e2;
                    cs1 += e1 + e3;
                }
                c[0] = c[1] = c[2] = c[3] = 0.0f;
            }
#pragma unroll
            for (int o = 4; o < 32; o <<= 1) {
                cs0 += __shfl_xor_sync(0xffffffffu, cs0, o);
                cs1 += __shfl_xor_sync(0xffffffffu, cs1, o);
            }
            if ((lane >> 2) == 0) {
                const int lc = nbase + nf * 8 + lane * 2;
                atomicAdd(dn + lc, cs0);
                atomicAdd(dn + lc + 1, cs1);
            }
        }
    };

    dec(0);
    dec(1);
    const int totq = nt * 4;
    stage_ld(0); CP_COMMIT;
    stage_ld(1); CP_COMMIT;

    for (int q = 0; q < totq; ++q) {
        asm volatile("cp.async.wait_group 1;");
        __syncthreads();
        if (q + 2 < totq) stage_ld(q + 2);
        CP_COMMIT;
        const uint32_t bA = sb + (q % 3) * (2 * TILEB);
        const uint32_t bB = bA + TILEB;
#pragma unroll
        for (int ks = 0; ks < 4; ++ks) {
            const int koff = ks * 16;
            uint32_t ah[2][4], bh[4][4];
#pragma unroll
            for (int mf = 0; mf < 2; ++mf) {
                const uint32_t ad = bA +
                    ((mbase + mf * 16 + (lane & 15)) * PITCH + koff + (lane >> 4) * 8) * 2;
                ldsm4(ah[mf], ad);
            }
#pragma unroll
            for (int nq = 0; nq < 4; ++nq) {
                const uint32_t bd = bB +
                    ((nbase + nq * 16 + (lane & 7) + ((lane >> 4) & 1) * 8) * PITCH +
                     koff + ((lane >> 3) & 1) * 8) * 2;
                ldsm4(bh[nq], bd);
            }
#pragma unroll
            for (int mf = 0; mf < 2; ++mf)
#pragma unroll
                for (int nf = 0; nf < 8; ++nf)
                    mma_f16(acc[mf][nf], ah[mf], &bh[nf >> 1][(nf & 1) * 2]);
        }
        if ((q & 3) == 3) {
            const int tl = q >> 2;
            epi(tl & 1);
            dec(tl + 2);  // same parity slot as tl, now free
        }
    }
}

// ---------------------------------------------------------------------------
// Kernel C: Out = 64*(E/64).V'^T (+V'[0]), balanced split-K, 3-stage.
// ---------------------------------------------------------------------------
__global__ __launch_bounds__(256, 2) void out_g(float* __restrict__ Out) {
    extern __shared__ __align__(16) char sm[];
    const int bx = blockIdx.x;
    int j, b, dt, half;
    bool split;
    if (bx < 256) {
        split = true;
        j = bx >> 4;
        b = (bx >> 2) & 3;
        dt = (bx >> 1) & 1;
        half = bx & 1;
    } else {
        split = false;
        const int t = bx - 256;
        j = 16 + (t >> 3);
        b = (t >> 1) & 3;
        dt = t & 1;
        half = 0;
    }
    const int n0 = j * 128, d0 = dt * 128;
    const __half* E = g_Eh + (size_t)b * NN * NN;
    const __half* VT = g_VTh + (size_t)b * ND * NN;

    int c0 = 2 * j, c1 = NN / 64;
    if (split) {
        const int cmid = 32 + j;
        if (half == 0) c1 = cmid; else c0 = cmid;
    }
    const bool addv0 = (j >= 1) && (half == 0);

    float* v0s = (float*)(sm + 3 * 2 * TILEB);
    if (addv0 && threadIdx.x < 128)
        v0s[threadIdx.x] = g_V0[b * ND + d0 + threadIdx.x];

    float acc[2][8][4];
    gemm_ml<1, 3, true>(E, nullptr, VT, n0, NN, d0, NN, c0, c1, sm, acc);

    const int wid = threadIdx.x >> 5, lane = threadIdx.x & 31;
    const int mbase = (wid >> 1) * 32, nbase = (wid & 1) * 64;
#pragma unroll
    for (int mf = 0; mf < 2; ++mf)
#pragma unroll
        for (int nf = 0; nf < 8; ++nf) {
            const int n = n0 + mbase + mf * 16 + (lane >> 2);
            const int lc = nbase + nf * 8 + (lane & 3) * 2;
            const int d = d0 + lc;
            float a0 = 0.f, a1 = 0.f;
            if (addv0) { a0 = v0s[lc]; a1 = v0s[lc + 1]; }
            float* c = acc[mf][nf];
            float* o0 = &Out[((size_t)b * NN + n) * ND + d];
            float* o1 = &Out[((size_t)b * NN + n + 8) * ND + d];
            if (split) {
                atomicAdd(o0, S64 * c[0] + a0);
                atomicAdd(o0 + 1, S64 * c[1] + a1);
                atomicAdd(o1, S64 * c[2] + a0);
                atomicAdd(o1 + 1, S64 * c[3] + a1);
            } else {
                *(float2*)o0 = make_float2(S64 * c[0] + a0, S64 * c[1] + a1);
                *(float2*)o1 = make_float2(S64 * c[2] + a0, S64 * c[3] + a1);
            }
        }
}

// ---------------------------------------------------------------------------
extern "C" void kernel_launch(void* const* d_in, const int* in_sizes, int n_in,
                              void* d_out, int out_size)
{
    const float* x  = (const float*)d_in[0];
    const float* Wq = (const float*)d_in[1];
    const float* Wk = (const float*)d_in[2];
    const float* Wv = (const float*)d_in[3];
    float* out = (float*)d_out;

    cudaFuncSetAttribute(qkv_g, cudaFuncAttributeMaxDynamicSharedMemorySize, QK_SMEM);
    cudaFuncSetAttribute(e_g,   cudaFuncAttributeMaxDynamicSharedMemorySize, E_SMEM);
    cudaFuncSetAttribute(out_g, cudaFuncAttributeMaxDynamicSharedMemorySize, O_SMEM);

    prep_kernel<<<4352, 256>>>(x, Wq, Wk, Wv, out);
    qkv_g<<<dim3(NB * NN / 128, ND / 128, 3), 256, QK_SMEM>>>();
    e_g<<<NCTA, 256, E_SMEM>>>();
    scale_t_g<<<dim3(NN / 64, ND / 64, NB), 256>>>();
    out_g<<<384, 256, O_SMEM>>>(out);
}

// round 15
// speedup vs baseline: 1.0609x; 1.0609x over previous
#include <cuda_runtime.h>
#include <cuda_fp16.h>
#include <cstdint>

#define NB 4
#define NN 4096
#define ND 256
#define SCL2 0.0901684403f   // (1/16) * log2(e)
#define S64 64.0f

// ---------------------------------------------------------------------------
// Device scratch
// ---------------------------------------------------------------------------
__device__ __align__(16) __half g_Xh[NB * NN * ND];
__device__ __align__(16) __half g_Xl[NB * NN * ND];
__device__ __align__(16) __half g_Wh[3 * ND * ND];
__device__ __align__(16) __half g_Qh[NB * NN * ND];
__device__ __align__(16) __half g_Kh[NB * NN * ND];
__device__ __align__(16) __half g_Vh[NB * NN * ND];         // V projection, fp16
__device__ __align__(16) __half g_VTh[NB * ND * NN];        // [b][d][m] scaled
__device__ __align__(16) __half g_Eh[(size_t)NB * NN * NN]; // 134 MB, = E/64
__device__ float g_denom[NB * NN];                          // scaled: sum(E)/64
__device__ float g_V0[NB * ND];                             // V'[m=0][d]

// ---------------------------------------------------------------------------
// PTX helpers
// ---------------------------------------------------------------------------
__device__ __forceinline__ uint32_t smem_u32(const void* p) {
    uint32_t a;
    asm("{ .reg .u64 t; cvta.to.shared.u64 t, %1; cvt.u32.u64 %0, t; }"
        : "=r"(a) : "l"(p));
    return a;
}

#define CP_ASYNC16(s, g) \
    asm volatile("cp.async.cg.shared.global [%0], [%1], 16;" :: "r"(s), "l"(g) : "memory")
#define CP_ASYNC16_CA(s, g) \
    asm volatile("cp.async.ca.shared.global [%0], [%1], 16;" :: "r"(s), "l"(g) : "memory")
#define CP_COMMIT asm volatile("cp.async.commit_group;" ::: "memory")

__device__ __forceinline__ void ldsm4(uint32_t* r, uint32_t addr) {
    asm volatile("ldmatrix.sync.aligned.m8n8.x4.shared.b16 {%0,%1,%2,%3}, [%4];"
                 : "=r"(r[0]), "=r"(r[1]), "=r"(r[2]), "=r"(r[3]) : "r"(addr));
}

__device__ __forceinline__ void mma_f16(float* c, const uint32_t* a, const uint32_t* b) {
    asm volatile(
        "mma.sync.aligned.m16n8k16.row.col.f32.f16.f16.f32 "
        "{%0,%1,%2,%3}, {%4,%5,%6,%7}, {%8,%9}, {%0,%1,%2,%3};"
        : "+f"(c[0]), "+f"(c[1]), "+f"(c[2]), "+f"(c[3])
        : "r"(a[0]), "r"(a[1]), "r"(a[2]), "r"(a[3]), "r"(b[0]), "r"(b[1]));
}

// single-MUFU packed exponential: e = 2^z for two halfs
__device__ __forceinline__ uint32_t ex2_f16x2(uint32_t z) {
    uint32_t r;
    asm("ex2.approx.f16x2 %0, %1;" : "=r"(r) : "r"(z));
    return r;
}

__device__ __forceinline__ void splith(float v, __half& h, __half& l) {
    h = __float2half_rn(v);
    l = __float2half_rn(v - __half2float(h));
}

// ---------------------------------------------------------------------------
// Tiles: 128 rows x 64 cols fp16, SMEM row pitch 72 elems (144 B), BCF.
// ---------------------------------------------------------------------------
#define PITCH 72
#define TILEB (128 * PITCH * 2)  // 18432

template <bool CA>
__device__ __forceinline__ void ld_tile(uint32_t sbase, const __half* src,
                                        int row0, int ld, int k0) {
    const int t = threadIdx.x;
#pragma unroll
    for (int h = 0; h < 4; ++h) {
        const int c = t + h * 256;
        const int row = c >> 3, seg = c & 7;
        const char* g = (const char*)src + ((size_t)(row0 + row) * ld + k0 + seg * 8) * 2;
        const uint32_t s = sbase + (row * PITCH + seg * 8) * 2;
        if (CA) { CP_ASYNC16_CA(s, g); } else { CP_ASYNC16(s, g); }
    }
}

// ---------------------------------------------------------------------------
// Generic NT fp16 mainloop (qkv / out_g), BM=BN=128, BK=64, 8 warps.
// CH=1: Ah.Bh | CH=2: (Ah+Al).Bh.  CAB: use .ca (L1) for the B operand.
// (R13 structure: wait -> sync -> compute -> sync, prefetch before wait)
// ---------------------------------------------------------------------------
template <int CH, int STAGES, bool CAB>
__device__ __forceinline__ void gemm_ml(
    const __half* Ah, const __half* Al, const __half* Bh,
    int rowA0, int ldA, int rowB0, int ldB,
    int c0, int c1, char* smp, float acc[2][8][4])
{
    constexpr int NT = (CH == 1) ? 2 : 3;
    constexpr int STG = NT * TILEB;
    constexpr int BOFF = (CH >= 2) ? 2 * TILEB : TILEB;
    const uint32_t sb = smem_u32(smp);
    const int wid = threadIdx.x >> 5, lane = threadIdx.x & 31;
    const int mbase = (wid >> 1) * 32, nbase = (wid & 1) * 64;

#pragma unroll
    for (int i = 0; i < 2; ++i)
#pragma unroll
        for (int j = 0; j < 8; ++j)
#pragma unroll
            for (int k = 0; k < 4; ++k) acc[i][j][k] = 0.0f;

    auto stage_ld = [&](int i, int s) {
        const uint32_t b = sb + s * STG;
        const int k0 = i * 64;
        ld_tile<false>(b, Ah, rowA0, ldA, k0);
        if (CH >= 2) ld_tile<false>(b + TILEB, Al, rowA0, ldA, k0);
        ld_tile<CAB>(b + BOFF, Bh, rowB0, ldB, k0);
    };

#pragma unroll
    for (int p = 0; p < STAGES - 1; ++p) {
        if (c0 + p < c1) stage_ld(c0 + p, p);
        CP_COMMIT;
    }

    int scur = 0, spre = STAGES - 1;
    for (int i = c0; i < c1; ++i) {
        if (i + STAGES - 1 < c1) stage_ld(i + STAGES - 1, spre);
        CP_COMMIT;
        if (++spre == STAGES) spre = 0;
        asm volatile("cp.async.wait_group %0;" :: "n"(STAGES - 1));
        __syncthreads();
        const uint32_t bA = sb + scur * STG;
        if (++scur == STAGES) scur = 0;
        const uint32_t bB = bA + BOFF;
#pragma unroll
        for (int ks = 0; ks < 4; ++ks) {
            const int koff = ks * 16;
            uint32_t ah[2][4], al[2][4], bh[4][4];
#pragma unroll
            for (int mf = 0; mf < 2; ++mf) {
                const uint32_t ad = bA +
                    ((mbase + mf * 16 + (lane & 15)) * PITCH + koff + (lane >> 4) * 8) * 2;
                ldsm4(ah[mf], ad);
                if (CH >= 2) ldsm4(al[mf], ad + TILEB);
            }
#pragma unroll
            for (int nq = 0; nq < 4; ++nq) {
                const uint32_t bd = bB +
                    ((nbase + nq * 16 + (lane & 7) + ((lane >> 4) & 1) * 8) * PITCH +
                     koff + ((lane >> 3) & 1) * 8) * 2;
                ldsm4(bh[nq], bd);
            }
#pragma unroll
            for (int mf = 0; mf < 2; ++mf)
#pragma unroll
                for (int nf = 0; nf < 8; ++nf) {
                    uint32_t* pb = &bh[nf >> 1][(nf & 1) * 2];
                    mma_f16(acc[mf][nf], ah[mf], pb);
                    if (CH >= 2) mma_f16(acc[mf][nf], al[mf], pb);
                }
        }
        __syncthreads();
    }
}

#define QK_SMEM (2 * 3 * TILEB)            // 110592
#define E_SMEM  (3 * 2 * TILEB)            // 110592 (3-stage x Q+K)
#define O_SMEM  (3 * 2 * TILEB + 512)      // 111104

// ---------------------------------------------------------------------------
// Fused prep: X split + FULL d_out zero | W fp16 | denom init
// ---------------------------------------------------------------------------
__global__ void prep_kernel(const float* __restrict__ x,
                            const float* __restrict__ Wq,
                            const float* __restrict__ Wk,
                            const float* __restrict__ Wv,
                            float* __restrict__ outp) {
    const int blk = blockIdx.x, t = threadIdx.x;
    if (blk < 4096) {
        const int i = blk * 256 + t;
        float4 v = ((const float4*)x)[i];
        __align__(8) __half h[4], l[4];
        splith(v.x, h[0], l[0]); splith(v.y, h[1], l[1]);
        splith(v.z, h[2], l[2]); splith(v.w, h[3], l[3]);
        ((uint2*)g_Xh)[i] = *(uint2*)h;
        ((uint2*)g_Xl)[i] = *(uint2*)l;
        ((float4*)outp)[i] = make_float4(0.f, 0.f, 0.f, 0.f);
    } else if (blk < 4288) {
        const int w = blk - 4096;
        const int z = w >> 6;
        const int i = (w & 63) * 256 + t;
        const float* W = (z == 0) ? Wq : (z == 1) ? Wk : Wv;
        float4 v = ((const float4*)W)[i];
        __align__(8) __half h[4];
        h[0] = __float2half_rn(v.x); h[1] = __float2half_rn(v.y);
        h[2] = __float2half_rn(v.z); h[3] = __float2half_rn(v.w);
        ((uint2*)(g_Wh + (size_t)z * ND * ND))[i] = *(uint2*)h;
    } else {
        const int i = (blk - 4288) * 256 + t;
        g_denom[i] = ((i & (NN - 1)) == 0) ? 62.0f : 0.0f;
    }
}

// ---------------------------------------------------------------------------
// V' = V * rcp(64*denom) -> transpose [b][d][m] fp16; also V'[0][d].
// ---------------------------------------------------------------------------
__global__ __launch_bounds__(256) void scale_t_g() {
    __shared__ float tile[64][65];
    __shared__ float rs[64];
    const int b = blockIdx.z;
    const int m0 = blockIdx.x * 64, d0 = blockIdx.y * 64;
    const int t = threadIdx.x;

    if (t < 64) rs[t] = __frcp_rn(S64 * g_denom[b * NN + m0 + t]);
    {
        const int m = t >> 2, ds = (t & 3) * 16;
        const __half* src = g_Vh + ((size_t)b * NN + m0 + m) * ND + d0 + ds;
        uint4 v0 = *(const uint4*)src;
        uint4 v1 = *(const uint4*)(src + 8);
        const __half* hp0 = (const __half*)&v0;
        const __half* hp1 = (const __half*)&v1;
#pragma unroll
        for (int k = 0; k < 8; ++k) tile[m][ds + k] = __half2float(hp0[k]);
#pragma unroll
        for (int k = 0; k < 8; ++k) tile[m][ds + 8 + k] = __half2float(hp1[k]);
    }
    __syncthreads();
    {
        const int d = t >> 2, ms = (t & 3) * 16;
        __align__(16) __half o[16];
#pragma unroll
        for (int k = 0; k < 16; ++k)
            o[k] = __float2half_rn(tile[ms + k][d] * rs[ms + k]);
        __half* dst = g_VTh + ((size_t)b * ND + d0 + d) * NN + m0 + ms;
        *(uint4*)dst = ((uint4*)o)[0];
        *(uint4*)(dst + 8) = ((uint4*)o)[1];
    }
    if (m0 == 0 && (t & 3) == 0) {
        const int d = t >> 2;
        g_V0[b * ND + d0 + d] = tile[0][d] * rs[0];
    }
}

// ---------------------------------------------------------------------------
// Kernel A: unified QKV projections (all 2-chain). grid (128, 2, 3)
// ---------------------------------------------------------------------------
__global__ __launch_bounds__(256, 2) void qkv_g() {
    extern __shared__ __align__(16) char sm[];
    const int z = blockIdx.z;
    const int tok0 = blockIdx.x * 128;
    const int c0b = blockIdx.y * 128;
    float acc[2][8][4];
    gemm_ml<2, 2, true>(g_Xh, g_Xl, g_Wh + (size_t)z * ND * ND,
                        tok0, ND, c0b, ND, 0, ND / 64, sm, acc);

    const int wid = threadIdx.x >> 5, lane = threadIdx.x & 31;
    const int mbase = (wid >> 1) * 32, nbase = (wid & 1) * 64;
    __half* dst = (z == 0) ? g_Qh : (z == 1) ? g_Kh : g_Vh;
#pragma unroll
    for (int mf = 0; mf < 2; ++mf)
#pragma unroll
        for (int nf = 0; nf < 8; ++nf) {
            const int tok = tok0 + mbase + mf * 16 + (lane >> 2);
            const int ch = c0b + nbase + nf * 8 + (lane & 3) * 2;
            float* c = acc[mf][nf];
            *(__half2*)&dst[(size_t)tok * ND + ch] = __floats2half2_rn(c[0], c[1]);
            *(__half2*)&dst[(size_t)(tok + 8) * ND + ch] = __floats2half2_rn(c[2], c[3]);
        }
}

// ---------------------------------------------------------------------------
// Kernel B: E/64 + scaled column sums. Single-chain Qh.Kh (tf32-quality).
// TWO triangular tiles per CTA, flat 8-chunk 3-STAGE pipeline. grid (264,1,4).
// ---------------------------------------------------------------------------
__device__ __forceinline__ float maskexp_s(int qn, int km, float z) {
    return (qn < km) ? exp2f(fmaf(z, SCL2, -6.0f)) : (km == 0 ? 0.015625f : 0.0f);
}

__global__ __launch_bounds__(256, 2) void e_g() {
    extern __shared__ __align__(16) char sm[];
    const int b = blockIdx.z;
    int m00, n00, dg0, m01, n01, dg1;
    {
        int t = blockIdx.x * 2;
        int it = (int)((sqrtf(8.0f * t + 1.0f) - 1.0f) * 0.5f);
        while ((it + 1) * (it + 2) / 2 <= t) ++it;
        while (it * (it + 1) / 2 > t) --it;
        int jt = t - it * (it + 1) / 2;
        m00 = it * 128; n00 = jt * 128; dg0 = (it == jt);
        if (++jt > it) { ++it; jt = 0; }
        m01 = it * 128; n01 = jt * 128; dg1 = (it == jt);
    }
    const size_t bo = (size_t)b * NN * ND;
    const __half* Qh = g_Qh + bo;
    const __half* Kh = g_Kh + bo;
    const uint32_t sb = smem_u32(sm);
    const int wid = threadIdx.x >> 5, lane = threadIdx.x & 31;
    const int mbase = (wid >> 1) * 32, nbase = (wid & 1) * 64;
    __half* Eb = g_Eh + (size_t)b * NN * NN;
    float* dnb = g_denom + b * NN;

    float acc[2][8][4];
#pragma unroll
    for (int i = 0; i < 2; ++i)
#pragma unroll
        for (int j = 0; j < 8; ++j)
#pragma unroll
            for (int k = 0; k < 4; ++k) acc[i][j][k] = 0.0f;

    auto stage_ld = [&](int c) {
        const int u = c >> 2, k0 = (c & 3) * 64;
        const int nn0 = u ? n01 : n00;
        const int mm0 = u ? m01 : m00;
        const uint32_t base = sb + (c % 3) * (2 * TILEB);
        ld_tile<false>(base, Qh, nn0, ND, k0);
        ld_tile<true>(base + TILEB, Kh, mm0, ND, k0);
    };

    auto epi = [&](int m0, int n0, int dgf) {
        float* dn = dnb + m0;
#pragma unroll
        for (int nf = 0; nf < 8; ++nf) {
            const int kb = m0 + nbase + nf * 8 + (lane & 3) * 2;
            float cs0 = 0.f, cs1 = 0.f;
#pragma unroll
            for (int mf = 0; mf < 2; ++mf) {
                const int qa = n0 + mbase + mf * 16 + (lane >> 2);
                float* c = acc[mf][nf];
                if (!dgf) {
                    __half2 ha = __floats2half2_rn(fmaf(c[0], SCL2, -6.0f),
                                                   fmaf(c[1], SCL2, -6.0f));
                    __half2 hb = __floats2half2_rn(fmaf(c[2], SCL2, -6.0f),
                                                   fmaf(c[3], SCL2, -6.0f));
                    uint32_t ea = ex2_f16x2(*(uint32_t*)&ha);
                    uint32_t eb = ex2_f16x2(*(uint32_t*)&hb);
                    *(uint32_t*)&Eb[(size_t)qa * NN + kb] = ea;
                    *(uint32_t*)&Eb[(size_t)(qa + 8) * NN + kb] = eb;
                    float2 fa = __half22float2(*(__half2*)&ea);
                    float2 fb = __half22float2(*(__half2*)&eb);
                    cs0 += fa.x + fb.x;
                    cs1 += fa.y + fb.y;
                } else {
                    const float e0 = maskexp_s(qa, kb, c[0]);
                    const float e1 = maskexp_s(qa, kb + 1, c[1]);
                    const float e2 = maskexp_s(qa + 8, kb, c[2]);
                    const float e3 = maskexp_s(qa + 8, kb + 1, c[3]);
                    *(__half2*)&Eb[(size_t)qa * NN + kb] = __floats2half2_rn(e0, e1);
                    *(__half2*)&Eb[(size_t)(qa + 8) * NN + kb] = __floats2half2_rn(e2, e3);
                    cs0 += e0 + e2;
                    cs1 += e1 + e3;
                }
                c[0] = c[1] = c[2] = c[3] = 0.0f;
            }
#pragma unroll
            for (int o = 4; o < 32; o <<= 1) {
                cs0 += __shfl_xor_sync(0xffffffffu, cs0, o);
                cs1 += __shfl_xor_sync(0xffffffffu, cs1, o);
            }
            if ((lane >> 2) == 0) {
                const int lc = nbase + nf * 8 + lane * 2;
                atomicAdd(dn + lc, cs0);
                atomicAdd(dn + lc + 1, cs1);
            }
        }
    };

    stage_ld(0); CP_COMMIT;
    stage_ld(1); CP_COMMIT;
    for (int c = 0; c < 8; ++c) {
        if (c + 2 < 8) stage_ld(c + 2);
        CP_COMMIT;
        asm volatile("cp.async.wait_group 2;");
        __syncthreads();
        const uint32_t bA = sb + (c % 3) * (2 * TILEB);
        const uint32_t bB = bA + TILEB;
#pragma unroll
        for (int ks = 0; ks < 4; ++ks) {
            const int koff = ks * 16;
            uint32_t ah[2][4], bh[4][4];
#pragma unroll
            for (int mf = 0; mf < 2; ++mf) {
                const uint32_t ad = bA +
                    ((mbase + mf * 16 + (lane & 15)) * PITCH + koff + (lane >> 4) * 8) * 2;
                ldsm4(ah[mf], ad);
            }
#pragma unroll
            for (int nq = 0; nq < 4; ++nq) {
                const uint32_t bd = bB +
                    ((nbase + nq * 16 + (lane & 7) + ((lane >> 4) & 1) * 8) * PITCH +
                     koff + ((lane >> 3) & 1) * 8) * 2;
                ldsm4(bh[nq], bd);
            }
#pragma unroll
            for (int mf = 0; mf < 2; ++mf)
#pragma unroll
                for (int nf = 0; nf < 8; ++nf)
                    mma_f16(acc[mf][nf], ah[mf], &bh[nf >> 1][(nf & 1) * 2]);
        }
        __syncthreads();
        if (c == 3) epi(m00, n00, dg0);
    }
    epi(m01, n01, dg1);
}

// ---------------------------------------------------------------------------
// Kernel C: Out = 64*(E/64).V'^T (+V'[0]), balanced split-K, 3-stage.
// ---------------------------------------------------------------------------
__global__ __launch_bounds__(256, 2) void out_g(float* __restrict__ Out) {
    extern __shared__ __align__(16) char sm[];
    const int bx = blockIdx.x;
    int j, b, dt, half;
    bool split;
    if (bx < 256) {
        split = true;
        j = bx >> 4;
        b = (bx >> 2) & 3;
        dt = (bx >> 1) & 1;
        half = bx & 1;
    } else {
        split = false;
        const int t = bx - 256;
        j = 16 + (t >> 3);
        b = (t >> 1) & 3;
        dt = t & 1;
        half = 0;
    }
    const int n0 = j * 128, d0 = dt * 128;
    const __half* E = g_Eh + (size_t)b * NN * NN;
    const __half* VT = g_VTh + (size_t)b * ND * NN;

    int c0 = 2 * j, c1 = NN / 64;
    if (split) {
        const int cmid = 32 + j;
        if (half == 0) c1 = cmid; else c0 = cmid;
    }
    const bool addv0 = (j >= 1) && (half == 0);

    float* v0s = (float*)(sm + 3 * 2 * TILEB);
    if (addv0 && threadIdx.x < 128)
        v0s[threadIdx.x] = g_V0[b * ND + d0 + threadIdx.x];

    float acc[2][8][4];
    gemm_ml<1, 3, true>(E, nullptr, VT, n0, NN, d0, NN, c0, c1, sm, acc);

    const int wid = threadIdx.x >> 5, lane = threadIdx.x & 31;
    const int mbase = (wid >> 1) * 32, nbase = (wid & 1) * 64;
#pragma unroll
    for (int mf = 0; mf < 2; ++mf)
#pragma unroll
        for (int nf = 0; nf < 8; ++nf) {
            const int n = n0 + mbase + mf * 16 + (lane >> 2);
            const int lc = nbase + nf * 8 + (lane & 3) * 2;
            const int d = d0 + lc;
            float a0 = 0.f, a1 = 0.f;
            if (addv0) { a0 = v0s[lc]; a1 = v0s[lc + 1]; }
            float* c = acc[mf][nf];
            float* o0 = &Out[((size_t)b * NN + n) * ND + d];
            float* o1 = &Out[((size_t)b * NN + n + 8) * ND + d];
            if (split) {
                atomicAdd(o0, S64 * c[0] + a0);
                atomicAdd(o0 + 1, S64 * c[1] + a1);
                atomicAdd(o1, S64 * c[2] + a0);
                atomicAdd(o1 + 1, S64 * c[3] + a1);
            } else {
                *(float2*)o0 = make_float2(S64 * c[0] + a0, S64 * c[1] + a1);
                *(float2*)o1 = make_float2(S64 * c[2] + a0, S64 * c[3] + a1);
            }
        }
}

// ---------------------------------------------------------------------------
extern "C" void kernel_launch(void* const* d_in, const int* in_sizes, int n_in,
                              void* d_out, int out_size)
{
    const float* x  = (const float*)d_in[0];
    const float* Wq = (const float*)d_in[1];
    const float* Wk = (const float*)d_in[2];
    const float* Wv = (const float*)d_in[3];
    float* out = (float*)d_out;

    cudaFuncSetAttribute(qkv_g, cudaFuncAttributeMaxDynamicSharedMemorySize, QK_SMEM);
    cudaFuncSetAttribute(e_g,   cudaFuncAttributeMaxDynamicSharedMemorySize, E_SMEM);
    cudaFuncSetAttribute(out_g, cudaFuncAttributeMaxDynamicSharedMemorySize, O_SMEM);

    prep_kernel<<<4352, 256>>>(x, Wq, Wk, Wv, out);
    qkv_g<<<dim3(NB * NN / 128, ND / 128, 3), 256, QK_SMEM>>>();
    e_g<<<dim3(264, 1, NB), 256, E_SMEM>>>();
    scale_t_g<<<dim3(NN / 64, ND / 64, NB), 256>>>();
    out_g<<<384, 256, O_SMEM>>>(out);
}